// round 10
// baseline (speedup 1.0000x reference)
#include <cuda_runtime.h>
#include <math.h>
#include <stdint.h>

// Problem dims
#define SS   4096
#define TT   64
#define II   64
#define EHH  128
#define EE   256
#define HH   512
#define H4   2048
#define KK   (EE + HH)   // 768 combined K for gates GEMM
#define OO   128
#define FF1  256
#define FF2  64
#define LGG  32

// GEMM tile config
#define BM 128
#define BN 128
#define BK 8
#define TM 8
#define TN 8
#define NTHREADS 256

// ---------------- device scratch (static; no allocation) ----------------
// NOTE: these are ONLY accessed via cudaGetSymbolAddress on the host side,
// never named directly in host expressions (that yields the host shadow
// address, which ATS silently maps to host RAM — the bug of rounds 1-8).
__device__ float g_laneC;                       // device-code-only access
__device__ float g_y1[(size_t)SS * TT * EHH];
__device__ float g_xemb[(size_t)TT * SS * EE];
__device__ float g_h[SS * HH];
__device__ float g_hraw[SS * HH];
__device__ float g_c[SS * HH];
__device__ float g_gates[(size_t)SS * H4];
__device__ float g_wcomb[(size_t)H4 * KK];
__device__ float g_bcomb[H4];
__device__ float g_o1[SS * OO];
__device__ float g_o2[SS * FF1];
__device__ float g_o3[SS * FF2];

__device__ __forceinline__ float sigmoidf(float x) {
    return 1.0f / (1.0f + expf(-x));
}

// ---------------- tiny kernels ----------------
__global__ void lane_kernel(const float* __restrict__ lane,
                            const float* __restrict__ Wlg1, const float* __restrict__ blg1,
                            const float* __restrict__ Wlg2, const float* __restrict__ blg2) {
    if (threadIdx.x == 0) {
        float l = lane[0];
        float acc = blg2[0];
        for (int j = 0; j < LGG; j++) {
            float v = fmaxf(l * Wlg1[j] + blg1[j], 0.0f);
            acc += v * Wlg2[j];
        }
        g_laneC = 1.0f / (1.0f + expf(-acc));   // device-side symbol write
    }
}

__global__ void prep_wcomb(const float* __restrict__ Wih, const float* __restrict__ bih,
                           const float* __restrict__ Whh, const float* __restrict__ bhh,
                           float* __restrict__ wcomb, float* __restrict__ bcomb) {
    int idx = blockIdx.x * blockDim.x + threadIdx.x;
    if (idx < H4 * KK) {
        int j = idx / KK, k = idx % KK;
        wcomb[idx] = (k < EE) ? Wih[j * EE + k] : Whh[j * HH + (k - EE)];
    }
    if (idx < H4) bcomb[idx] = bih[idx] + bhh[idx];
}

__global__ void init_hc(float* __restrict__ h, float* __restrict__ c) {
    int idx = blockIdx.x * blockDim.x + threadIdx.x;
    if (idx < SS * HH) { h[idx] = 0.0f; c[idx] = 0.0f; }
}

// ---------------- tiled fp32 GEMM: C = act(A[M,K] @ B[N,K]^T + bias) ----------------
template <bool SCALEA, bool RELU, bool REMAP>
__global__ void __launch_bounds__(NTHREADS)
gemm_kernel(const float* __restrict__ A, const float* __restrict__ B,
            const float* __restrict__ bias, float* __restrict__ Cout,
            int M, int N, int K) {
    __shared__ float As[BK][BM + 4];
    __shared__ float Bs[BK][BN + 4];

    const int tid = threadIdx.x;
    const int tx = tid & 15;
    const int ty = tid >> 4;
    const int m0 = blockIdx.y * BM;
    const int n0 = blockIdx.x * BN;

    float acc[TM][TN];
#pragma unroll
    for (int i = 0; i < TM; i++)
#pragma unroll
        for (int j = 0; j < TN; j++) acc[i][j] = 0.0f;

    const float scale = SCALEA ? g_laneC : 1.0f;  // device-side symbol read

    for (int k0 = 0; k0 < K; k0 += BK) {
#pragma unroll
        for (int l = 0; l < (BM * BK) / NTHREADS; l++) {
            int idx = tid + l * NTHREADS;
            int r = idx >> 3, c = idx & 7;
            int gm = m0 + r;
            float v = (gm < M) ? A[(size_t)gm * K + (k0 + c)] : 0.0f;
            As[c][r] = v * scale;
        }
#pragma unroll
        for (int l = 0; l < (BN * BK) / NTHREADS; l++) {
            int idx = tid + l * NTHREADS;
            int r = idx >> 3, c = idx & 7;
            int gn = n0 + r;
            float v = (gn < N) ? B[(size_t)gn * K + (k0 + c)] : 0.0f;
            Bs[c][r] = v;
        }
        __syncthreads();

#pragma unroll
        for (int k = 0; k < BK; k++) {
            float a[TM], b[TN];
#pragma unroll
            for (int i = 0; i < TM; i++) a[i] = As[k][ty * TM + i];
#pragma unroll
            for (int j = 0; j < TN; j++) b[j] = Bs[k][tx * TN + j];
#pragma unroll
            for (int i = 0; i < TM; i++)
#pragma unroll
                for (int j = 0; j < TN; j++) acc[i][j] += a[i] * b[j];
        }
        __syncthreads();
    }

#pragma unroll
    for (int i = 0; i < TM; i++) {
        int gm = m0 + ty * TM + i;
        if (gm >= M) continue;
        size_t orow = gm;
        if (REMAP) orow = (size_t)(gm % TT) * SS + (size_t)(gm / TT);
#pragma unroll
        for (int j = 0; j < TN; j++) {
            int gn = n0 + tx * TN + j;
            if (gn < N) {
                float v = acc[i][j] + bias[gn];
                if (RELU) v = fmaxf(v, 0.0f);
                Cout[orow * (size_t)N + gn] = v;
            }
        }
    }
}

// ---------------- gates GEMM: [S,768] x [2048,768]^T, A split x||h ----------------
__global__ void __launch_bounds__(NTHREADS)
gemm_gates(const float* __restrict__ Ax, const float* __restrict__ hprev,
           const float* __restrict__ wcomb, const float* __restrict__ bcomb,
           float* __restrict__ gates) {
    __shared__ float As[BK][BM + 4];
    __shared__ float Bs[BK][BN + 4];

    const int tid = threadIdx.x;
    const int tx = tid & 15;
    const int ty = tid >> 4;
    const int m0 = blockIdx.y * BM;
    const int n0 = blockIdx.x * BN;

    float acc[TM][TN];
#pragma unroll
    for (int i = 0; i < TM; i++)
#pragma unroll
        for (int j = 0; j < TN; j++) acc[i][j] = 0.0f;

    for (int k0 = 0; k0 < KK; k0 += BK) {
#pragma unroll
        for (int l = 0; l < (BM * BK) / NTHREADS; l++) {
            int idx = tid + l * NTHREADS;
            int r = idx >> 3, c = idx & 7;
            int gm = m0 + r, gk = k0 + c;
            float v = (gk < EE) ? Ax[(size_t)gm * EE + gk]
                                : hprev[(size_t)gm * HH + (gk - EE)];
            As[c][r] = v;
        }
#pragma unroll
        for (int l = 0; l < (BN * BK) / NTHREADS; l++) {
            int idx = tid + l * NTHREADS;
            int r = idx >> 3, c = idx & 7;
            int gn = n0 + r;
            Bs[c][r] = wcomb[(size_t)gn * KK + (k0 + c)];
        }
        __syncthreads();

#pragma unroll
        for (int k = 0; k < BK; k++) {
            float a[TM], b[TN];
#pragma unroll
            for (int i = 0; i < TM; i++) a[i] = As[k][ty * TM + i];
#pragma unroll
            for (int j = 0; j < TN; j++) b[j] = Bs[k][tx * TN + j];
#pragma unroll
            for (int i = 0; i < TM; i++)
#pragma unroll
                for (int j = 0; j < TN; j++) acc[i][j] += a[i] * b[j];
        }
        __syncthreads();
    }

#pragma unroll
    for (int i = 0; i < TM; i++) {
        int gm = m0 + ty * TM + i;
#pragma unroll
        for (int j = 0; j < TN; j++) {
            int gn = n0 + tx * TN + j;
            gates[(size_t)gm * H4 + gn] = acc[i][j] + bcomb[gn];
        }
    }
}

// ---------------- LSTM pointwise + spatial maxpool ----------------
__global__ void lstm_pointwise(const float* __restrict__ gates,
                               float* __restrict__ c, float* __restrict__ hraw) {
    int idx = blockIdx.x * blockDim.x + threadIdx.x;
    if (idx >= SS * HH) return;
    int s = idx / HH, j = idx % HH;
    const float* g = gates + (size_t)s * H4;
    float ig = sigmoidf(g[j]);
    float fg = sigmoidf(g[HH + j]);
    float gg = tanhf(g[2 * HH + j]);
    float og = sigmoidf(g[3 * HH + j]);
    float cv = fg * c[idx] + ig * gg;
    c[idx] = cv;
    hraw[idx] = og * tanhf(cv);
}

__global__ void maxpool_kernel(const float* __restrict__ hraw, float* __restrict__ h) {
    int idx = blockIdx.x * blockDim.x + threadIdx.x;
    if (idx >= SS * HH) return;
    int s = idx / HH;
    float v = hraw[idx];
    if (s > 0)      v = fmaxf(v, hraw[idx - HH]);
    if (s < SS - 1) v = fmaxf(v, hraw[idx + HH]);
    h[idx] = v;
}

// ---------------- final dot + output assembly ----------------
__global__ void final_out(const float* __restrict__ Wf3, const float* __restrict__ bf3,
                          const float* __restrict__ o3, float* __restrict__ outp) {
    int warp = (blockIdx.x * blockDim.x + threadIdx.x) >> 5;
    int lane = threadIdx.x & 31;
    if (warp >= SS) return;
    const float* row = o3 + (size_t)warp * FF2;
    float v = row[lane] * Wf3[lane] + row[lane + 32] * Wf3[lane + 32];
#pragma unroll
    for (int o = 16; o; o >>= 1) v += __shfl_down_sync(0xffffffffu, v, o);
    if (lane == 0) outp[warp] = (v + bf3[0]) / g_laneC;
}

__global__ void copy_hc(const float* __restrict__ h, const float* __restrict__ c,
                        float* __restrict__ outp) {
    int idx = blockIdx.x * blockDim.x + threadIdx.x;
    if (idx >= SS * HH) return;
    outp[SS + idx] = h[idx];
    outp[SS + SS * HH + idx] = c[idx];
}

// ---------------- launch ----------------
extern "C" void kernel_launch(void* const* d_in, const int* in_sizes, int n_in,
                              void* d_out, int out_size) {
    // Bind inputs by element-count signature, greedy first-fit in dict order.
    static const int DICT_SIZES[22] = {
        16777216, 1, 32, 32, 32, 1, 8192, 128, 32768, 256, 524288,
        2048, 1048576, 2048, 65536, 128, 32768, 256, 16384, 64, 64, 1
    };
    const float* P[22];
    bool used[64];
    for (int i = 0; i < 64; i++) used[i] = false;
    bool ok = (n_in >= 22);
    for (int p = 0; p < 22 && ok; p++) {
        P[p] = nullptr;
        for (int i = 0; i < n_in; i++) {
            if (!used[i] && in_sizes[i] == DICT_SIZES[p]) {
                P[p] = (const float*)d_in[i];
                used[i] = true;
                break;
            }
        }
        if (!P[p]) ok = false;
    }
    if (!ok) {
        for (int p = 0; p < 22; p++) P[p] = (const float*)d_in[p];
    }

    const float* inputData = P[0];
    const float* lane  = P[1];
    const float* Wlg1  = P[2];  const float* blg1 = P[3];
    const float* Wlg2  = P[4];  const float* blg2 = P[5];
    const float* We1   = P[6];  const float* be1  = P[7];
    const float* We2   = P[8];  const float* be2  = P[9];
    const float* Wih   = P[10]; const float* bih  = P[11];
    const float* Whh   = P[12]; const float* bhh  = P[13];
    const float* Wout  = P[14]; const float* bout = P[15];
    const float* Wf1   = P[16]; const float* bf1  = P[17];
    const float* Wf2   = P[18]; const float* bf2  = P[19];
    const float* Wf3   = P[20]; const float* bf3  = P[21];

    // Proper DEVICE addresses of scratch buffers (cudaGetSymbolAddress is a
    // host-side query: no allocation, no stream op, graph-capture safe).
    float *y1, *xemb, *h, *hraw, *c, *gates, *wcomb, *bcomb, *o1, *o2, *o3;
    cudaGetSymbolAddress((void**)&y1,    g_y1);
    cudaGetSymbolAddress((void**)&xemb,  g_xemb);
    cudaGetSymbolAddress((void**)&h,     g_h);
    cudaGetSymbolAddress((void**)&hraw,  g_hraw);
    cudaGetSymbolAddress((void**)&c,     g_c);
    cudaGetSymbolAddress((void**)&gates, g_gates);
    cudaGetSymbolAddress((void**)&wcomb, g_wcomb);
    cudaGetSymbolAddress((void**)&bcomb, g_bcomb);
    cudaGetSymbolAddress((void**)&o1,    g_o1);
    cudaGetSymbolAddress((void**)&o2,    g_o2);
    cudaGetSymbolAddress((void**)&o3,    g_o3);

    float* outp = (float*)d_out;

    lane_kernel<<<1, 32>>>(lane, Wlg1, blg1, Wlg2, blg2);
    prep_wcomb<<<(H4 * KK + 255) / 256, 256>>>(Wih, bih, Whh, bhh, wcomb, bcomb);
    init_hc<<<(SS * HH + 255) / 256, 256>>>(h, c);

    // Embedding MLP: [S*T, I] -> [S*T, EH] -> [T,S,E]
    {
        dim3 g1(1, (SS * TT) / BM);
        gemm_kernel<true, true, false><<<g1, NTHREADS>>>(inputData, We1, be1, y1,
                                                         SS * TT, EHH, II);
        dim3 g2(EE / BN, (SS * TT) / BM);
        gemm_kernel<false, true, true><<<g2, NTHREADS>>>(y1, We2, be2, xemb,
                                                         SS * TT, EE, EHH);
    }

    // LSTM over time
    dim3 gg(H4 / BN, SS / BM);
    int pw_blocks = (SS * HH + 255) / 256;
    for (int t = 0; t < TT; t++) {
        gemm_gates<<<gg, NTHREADS>>>(xemb + (size_t)t * SS * EE, h, wcomb, bcomb, gates);
        lstm_pointwise<<<pw_blocks, 256>>>(gates, c, hraw);
        maxpool_kernel<<<pw_blocks, 256>>>(hraw, h);
    }

    // Output head
    gemm_kernel<false, false, false><<<dim3(1, SS / BM), NTHREADS>>>(h, Wout, bout, o1,
                                                                     SS, OO, HH);
    gemm_kernel<false, true, false><<<dim3(FF1 / BN, SS / BM), NTHREADS>>>(o1, Wf1, bf1, o2,
                                                                           SS, FF1, OO);
    gemm_kernel<false, true, false><<<dim3(1, SS / BM), NTHREADS>>>(o2, Wf2, bf2, o3,
                                                                    SS, FF2, FF1);
    final_out<<<(SS * 32 + 127) / 128, 128>>>(Wf3, bf3, o3, outp);
    if (out_size >= SS + 2 * SS * HH) {
        copy_hc<<<pw_blocks, 256>>>(h, c, outp);
    }
}

// round 11
// speedup vs baseline: 2.4123x; 2.4123x over previous
#include <cuda_runtime.h>
#include <cuda_bf16.h>
#include <math.h>
#include <stdint.h>

// Problem dims
#define SS   4096
#define TT   64
#define II   64
#define EHH  128
#define EE   256
#define HH   512
#define H4   2048
#define KK   (EE + HH)   // 768
#define OO   128
#define FF1  256
#define FF2  64
#define LGG  32

// SIMT GEMM tile config
#define BM 128
#define BN 128
#define BK 8
#define TM 8
#define TN 8
#define NTHREADS 256

// ---------------- device scratch (host access ONLY via cudaGetSymbolAddress) ----------------
__device__ float g_laneC;
__device__ float g_y1[(size_t)SS * TT * EHH];
__device__ __nv_bfloat16 g_xemb_hi[(size_t)TT * SS * EE];
__device__ __nv_bfloat16 g_xemb_lo[(size_t)TT * SS * EE];
__device__ float g_h[SS * HH];
__device__ __nv_bfloat16 g_h_hi[SS * HH];
__device__ __nv_bfloat16 g_h_lo[SS * HH];
__device__ float g_hraw[SS * HH];
__device__ float g_c[SS * HH];
__device__ float g_gates[(size_t)SS * H4];
__device__ __nv_bfloat16 g_wT_hi[(size_t)KK * H4];   // [768][2048]
__device__ __nv_bfloat16 g_wT_lo[(size_t)KK * H4];
__device__ float g_bcomb[H4];
__device__ float g_o1[SS * OO];
__device__ float g_o2[SS * FF1];
__device__ float g_o3[SS * FF2];

__device__ __forceinline__ float sigmoidf(float x) {
    return 1.0f / (1.0f + expf(-x));
}

__device__ __forceinline__ void split2(float v, __nv_bfloat16& hi, __nv_bfloat16& lo) {
    hi = __float2bfloat16(v);
    lo = __float2bfloat16(v - __bfloat162float(hi));
}

// ---------------- tiny kernels ----------------
__global__ void lane_kernel(const float* __restrict__ lane,
                            const float* __restrict__ Wlg1, const float* __restrict__ blg1,
                            const float* __restrict__ Wlg2, const float* __restrict__ blg2) {
    if (threadIdx.x == 0) {
        float l = lane[0];
        float acc = blg2[0];
        for (int j = 0; j < LGG; j++) {
            float v = fmaxf(l * Wlg1[j] + blg1[j], 0.0f);
            acc += v * Wlg2[j];
        }
        g_laneC = 1.0f / (1.0f + expf(-acc));
    }
}

// Build transposed combined weight [768][2048] split hi/lo, + combined bias.
__global__ void prep_w(const float* __restrict__ Wih, const float* __restrict__ bih,
                       const float* __restrict__ Whh, const float* __restrict__ bhh,
                       __nv_bfloat16* __restrict__ wThi, __nv_bfloat16* __restrict__ wTlo,
                       float* __restrict__ bcomb) {
    int idx = blockIdx.x * blockDim.x + threadIdx.x;
    if (idx < KK * H4) {
        int k = idx >> 11;          // / 2048
        int j = idx & (H4 - 1);
        float v = (k < EE) ? Wih[(size_t)j * EE + k] : Whh[(size_t)j * HH + (k - EE)];
        __nv_bfloat16 hi, lo;
        split2(v, hi, lo);
        wThi[idx] = hi; wTlo[idx] = lo;
    }
    if (idx < H4) bcomb[idx] = bih[idx] + bhh[idx];
}

__global__ void init_hc(float* __restrict__ h, float* __restrict__ c,
                        __nv_bfloat16* __restrict__ hhi, __nv_bfloat16* __restrict__ hlo) {
    int idx = blockIdx.x * blockDim.x + threadIdx.x;
    if (idx < SS * HH) {
        h[idx] = 0.0f; c[idx] = 0.0f;
        hhi[idx] = __float2bfloat16(0.0f); hlo[idx] = __float2bfloat16(0.0f);
    }
}

// ---------------- SIMT fp32 GEMM: C = act(A[M,K] @ B[N,K]^T + bias) ----------------
// SPLITOUT: write result as bf16 hi/lo pair instead of fp32.
template <bool SCALEA, bool RELU, bool REMAP, bool SPLITOUT>
__global__ void __launch_bounds__(NTHREADS)
gemm_kernel(const float* __restrict__ A, const float* __restrict__ B,
            const float* __restrict__ bias, float* __restrict__ Cout,
            __nv_bfloat16* __restrict__ Ohi, __nv_bfloat16* __restrict__ Olo,
            int M, int N, int K) {
    __shared__ float As[BK][BM + 4];
    __shared__ float Bs[BK][BN + 4];

    const int tid = threadIdx.x;
    const int tx = tid & 15;
    const int ty = tid >> 4;
    const int m0 = blockIdx.y * BM;
    const int n0 = blockIdx.x * BN;

    float acc[TM][TN];
#pragma unroll
    for (int i = 0; i < TM; i++)
#pragma unroll
        for (int j = 0; j < TN; j++) acc[i][j] = 0.0f;

    const float scale = SCALEA ? g_laneC : 1.0f;

    for (int k0 = 0; k0 < K; k0 += BK) {
#pragma unroll
        for (int l = 0; l < (BM * BK) / NTHREADS; l++) {
            int idx = tid + l * NTHREADS;
            int r = idx >> 3, c = idx & 7;
            int gm = m0 + r;
            float v = (gm < M) ? A[(size_t)gm * K + (k0 + c)] : 0.0f;
            As[c][r] = v * scale;
        }
#pragma unroll
        for (int l = 0; l < (BN * BK) / NTHREADS; l++) {
            int idx = tid + l * NTHREADS;
            int r = idx >> 3, c = idx & 7;
            int gn = n0 + r;
            float v = (gn < N) ? B[(size_t)gn * K + (k0 + c)] : 0.0f;
            Bs[c][r] = v;
        }
        __syncthreads();

#pragma unroll
        for (int k = 0; k < BK; k++) {
            float a[TM], b[TN];
#pragma unroll
            for (int i = 0; i < TM; i++) a[i] = As[k][ty * TM + i];
#pragma unroll
            for (int j = 0; j < TN; j++) b[j] = Bs[k][tx * TN + j];
#pragma unroll
            for (int i = 0; i < TM; i++)
#pragma unroll
                for (int j = 0; j < TN; j++) acc[i][j] += a[i] * b[j];
        }
        __syncthreads();
    }

#pragma unroll
    for (int i = 0; i < TM; i++) {
        int gm = m0 + ty * TM + i;
        if (gm >= M) continue;
        size_t orow = gm;
        if (REMAP) orow = (size_t)(gm % TT) * SS + (size_t)(gm / TT);
#pragma unroll
        for (int j = 0; j < TN; j++) {
            int gn = n0 + tx * TN + j;
            if (gn < N) {
                float v = acc[i][j] + bias[gn];
                if (RELU) v = fmaxf(v, 0.0f);
                size_t oidx = orow * (size_t)N + gn;
                if (SPLITOUT) {
                    __nv_bfloat16 hi, lo;
                    split2(v, hi, lo);
                    Ohi[oidx] = hi; Olo[oidx] = lo;
                } else {
                    Cout[oidx] = v;
                }
            }
        }
    }
}

// ---------------- bf16 tensor-core gates GEMM (3-term hi/lo split) ----------------
// gates[4096,2048] = [x_t || h] (K=768) @ wT + bcomb, fp32 accumulate.
#define MMA16816(d, a, b)                                                     \
    asm volatile(                                                             \
        "mma.sync.aligned.m16n8k16.row.col.f32.bf16.bf16.f32 "                \
        "{%0,%1,%2,%3}, {%4,%5,%6,%7}, {%8,%9}, {%0,%1,%2,%3};"               \
        : "+f"(d[0]), "+f"(d[1]), "+f"(d[2]), "+f"(d[3])                      \
        : "r"(a[0]), "r"(a[1]), "r"(a[2]), "r"(a[3]), "r"(b[0]), "r"(b[1]))

__global__ void __launch_bounds__(256)
gates_mma(const __nv_bfloat16* __restrict__ xhi, const __nv_bfloat16* __restrict__ xlo,
          const __nv_bfloat16* __restrict__ hhi, const __nv_bfloat16* __restrict__ hlo,
          const __nv_bfloat16* __restrict__ wThi, const __nv_bfloat16* __restrict__ wTlo,
          const float* __restrict__ bcomb, float* __restrict__ gates) {
    __shared__ __nv_bfloat16 Ahi[128][40];   // stride 40 b16 = 80B (16B-aligned rows)
    __shared__ __nv_bfloat16 Alo[128][40];
    __shared__ __nv_bfloat16 Bhi[32][136];   // stride 136 b16 = 272B
    __shared__ __nv_bfloat16 Blo[32][136];

    const int tid  = threadIdx.x;
    const int lane = tid & 31;
    const int w    = tid >> 5;
    const int wm   = w & 1;      // 2 warp-rows  (M 2x64)
    const int wn   = w >> 1;     // 4 warp-cols  (N 4x32)
    const int n0   = blockIdx.x * 128;
    const int s0   = blockIdx.y * 128;

    float acc[4][4][4];
#pragma unroll
    for (int mt = 0; mt < 4; mt++)
#pragma unroll
        for (int nt = 0; nt < 4; nt++)
#pragma unroll
            for (int e = 0; e < 4; e++) acc[mt][nt][e] = 0.0f;

    for (int k0 = 0; k0 < KK; k0 += 32) {
        // --- load A tile 128x32 (hi & lo): x part (k<256) or h part ---
        {
            int row = tid >> 1, half = tid & 1;
            const __nv_bfloat16 *sh, *sl;
            if (k0 < EE) {
                size_t off = (size_t)(s0 + row) * EE + k0 + half * 16;
                sh = xhi + off; sl = xlo + off;
            } else {
                size_t off = (size_t)(s0 + row) * HH + (k0 - EE) + half * 16;
                sh = hhi + off; sl = hlo + off;
            }
            uint4 v0 = *(const uint4*)sh;
            uint4 v1 = *(const uint4*)(sh + 8);
            *(uint4*)&Ahi[row][half * 16]     = v0;
            *(uint4*)&Ahi[row][half * 16 + 8] = v1;
            v0 = *(const uint4*)sl;
            v1 = *(const uint4*)(sl + 8);
            *(uint4*)&Alo[row][half * 16]     = v0;
            *(uint4*)&Alo[row][half * 16 + 8] = v1;
        }
        // --- load B tile 32x128 (hi & lo) from wT[768][2048] ---
#pragma unroll
        for (int it = 0; it < 2; it++) {
            int chunk = tid + it * 256;
            int row = chunk >> 4, c = chunk & 15;
            size_t off = (size_t)(k0 + row) * H4 + n0 + c * 8;
            *(uint4*)&Bhi[row][c * 8] = *(const uint4*)(wThi + off);
            *(uint4*)&Blo[row][c * 8] = *(const uint4*)(wTlo + off);
        }
        __syncthreads();

#pragma unroll
        for (int kk = 0; kk < 32; kk += 16) {
            uint32_t ah[4][4], al[4][4];
#pragma unroll
            for (int mt = 0; mt < 4; mt++) {
                int r = wm * 64 + mt * 16 + (lane >> 2);
                int c = kk + (lane & 3) * 2;
                ah[mt][0] = *(const uint32_t*)&Ahi[r][c];
                ah[mt][1] = *(const uint32_t*)&Ahi[r + 8][c];
                ah[mt][2] = *(const uint32_t*)&Ahi[r][c + 8];
                ah[mt][3] = *(const uint32_t*)&Ahi[r + 8][c + 8];
                al[mt][0] = *(const uint32_t*)&Alo[r][c];
                al[mt][1] = *(const uint32_t*)&Alo[r + 8][c];
                al[mt][2] = *(const uint32_t*)&Alo[r][c + 8];
                al[mt][3] = *(const uint32_t*)&Alo[r + 8][c + 8];
            }
            uint32_t bh[4][2], bl[4][2];
#pragma unroll
            for (int nt = 0; nt < 4; nt++) {
                int n = wn * 32 + nt * 8 + (lane >> 2);
                int k = kk + (lane & 3) * 2;
                bh[nt][0] = (uint32_t)*(const uint16_t*)&Bhi[k][n]
                          | ((uint32_t)*(const uint16_t*)&Bhi[k + 1][n] << 16);
                bh[nt][1] = (uint32_t)*(const uint16_t*)&Bhi[k + 8][n]
                          | ((uint32_t)*(const uint16_t*)&Bhi[k + 9][n] << 16);
                bl[nt][0] = (uint32_t)*(const uint16_t*)&Blo[k][n]
                          | ((uint32_t)*(const uint16_t*)&Blo[k + 1][n] << 16);
                bl[nt][1] = (uint32_t)*(const uint16_t*)&Blo[k + 8][n]
                          | ((uint32_t)*(const uint16_t*)&Blo[k + 9][n] << 16);
            }
#pragma unroll
            for (int mt = 0; mt < 4; mt++)
#pragma unroll
                for (int nt = 0; nt < 4; nt++) {
                    MMA16816(acc[mt][nt], ah[mt], bh[nt]);
                    MMA16816(acc[mt][nt], ah[mt], bl[nt]);
                    MMA16816(acc[mt][nt], al[mt], bh[nt]);
                }
        }
        __syncthreads();
    }

    // epilogue: + bcomb, write fp32 gates
#pragma unroll
    for (int mt = 0; mt < 4; mt++) {
        int r = s0 + wm * 64 + mt * 16 + (lane >> 2);
#pragma unroll
        for (int nt = 0; nt < 4; nt++) {
            int cn = n0 + wn * 32 + nt * 8 + (lane & 3) * 2;
            float b0 = bcomb[cn], b1 = bcomb[cn + 1];
            gates[(size_t)r * H4 + cn]           = acc[mt][nt][0] + b0;
            gates[(size_t)r * H4 + cn + 1]       = acc[mt][nt][1] + b1;
            gates[(size_t)(r + 8) * H4 + cn]     = acc[mt][nt][2] + b0;
            gates[(size_t)(r + 8) * H4 + cn + 1] = acc[mt][nt][3] + b1;
        }
    }
}

// ---------------- LSTM pointwise + spatial maxpool ----------------
__global__ void lstm_pointwise(const float* __restrict__ gates,
                               float* __restrict__ c, float* __restrict__ hraw) {
    int idx = blockIdx.x * blockDim.x + threadIdx.x;
    if (idx >= SS * HH) return;
    int s = idx / HH, j = idx % HH;
    const float* g = gates + (size_t)s * H4;
    float ig = sigmoidf(g[j]);
    float fg = sigmoidf(g[HH + j]);
    float gg = tanhf(g[2 * HH + j]);
    float og = sigmoidf(g[3 * HH + j]);
    float cv = fg * c[idx] + ig * gg;
    c[idx] = cv;
    hraw[idx] = og * tanhf(cv);
}

__global__ void maxpool_kernel(const float* __restrict__ hraw, float* __restrict__ h,
                               __nv_bfloat16* __restrict__ hhi, __nv_bfloat16* __restrict__ hlo) {
    int idx = blockIdx.x * blockDim.x + threadIdx.x;
    if (idx >= SS * HH) return;
    int s = idx / HH;
    float v = hraw[idx];
    if (s > 0)      v = fmaxf(v, hraw[idx - HH]);
    if (s < SS - 1) v = fmaxf(v, hraw[idx + HH]);
    h[idx] = v;
    __nv_bfloat16 hi, lo;
    split2(v, hi, lo);
    hhi[idx] = hi; hlo[idx] = lo;
}

// ---------------- final dot + output assembly ----------------
__global__ void final_out(const float* __restrict__ Wf3, const float* __restrict__ bf3,
                          const float* __restrict__ o3, float* __restrict__ outp) {
    int warp = (blockIdx.x * blockDim.x + threadIdx.x) >> 5;
    int lane = threadIdx.x & 31;
    if (warp >= SS) return;
    const float* row = o3 + (size_t)warp * FF2;
    float v = row[lane] * Wf3[lane] + row[lane + 32] * Wf3[lane + 32];
#pragma unroll
    for (int o = 16; o; o >>= 1) v += __shfl_down_sync(0xffffffffu, v, o);
    if (lane == 0) outp[warp] = (v + bf3[0]) / g_laneC;
}

__global__ void copy_hc(const float* __restrict__ h, const float* __restrict__ c,
                        float* __restrict__ outp) {
    int idx = blockIdx.x * blockDim.x + threadIdx.x;
    if (idx >= SS * HH) return;
    outp[SS + idx] = h[idx];
    outp[SS + SS * HH + idx] = c[idx];
}

// ---------------- launch ----------------
extern "C" void kernel_launch(void* const* d_in, const int* in_sizes, int n_in,
                              void* d_out, int out_size) {
    static const int DICT_SIZES[22] = {
        16777216, 1, 32, 32, 32, 1, 8192, 128, 32768, 256, 524288,
        2048, 1048576, 2048, 65536, 128, 32768, 256, 16384, 64, 64, 1
    };
    const float* P[22];
    bool used[64];
    for (int i = 0; i < 64; i++) used[i] = false;
    bool ok = (n_in >= 22);
    for (int p = 0; p < 22 && ok; p++) {
        P[p] = nullptr;
        for (int i = 0; i < n_in; i++) {
            if (!used[i] && in_sizes[i] == DICT_SIZES[p]) {
                P[p] = (const float*)d_in[i];
                used[i] = true;
                break;
            }
        }
        if (!P[p]) ok = false;
    }
    if (!ok) {
        for (int p = 0; p < 22; p++) P[p] = (const float*)d_in[p];
    }

    const float* inputData = P[0];
    const float* lane  = P[1];
    const float* Wlg1  = P[2];  const float* blg1 = P[3];
    const float* Wlg2  = P[4];  const float* blg2 = P[5];
    const float* We1   = P[6];  const float* be1  = P[7];
    const float* We2   = P[8];  const float* be2  = P[9];
    const float* Wih   = P[10]; const float* bih  = P[11];
    const float* Whh   = P[12]; const float* bhh  = P[13];
    const float* Wout  = P[14]; const float* bout = P[15];
    const float* Wf1   = P[16]; const float* bf1  = P[17];
    const float* Wf2   = P[18]; const float* bf2  = P[19];
    const float* Wf3   = P[20]; const float* bf3  = P[21];

    float *y1, *h, *hraw, *c, *gates, *bcomb, *o1, *o2, *o3;
    __nv_bfloat16 *xemb_hi, *xemb_lo, *h_hi, *h_lo, *wT_hi, *wT_lo;
    cudaGetSymbolAddress((void**)&y1,      g_y1);
    cudaGetSymbolAddress((void**)&xemb_hi, g_xemb_hi);
    cudaGetSymbolAddress((void**)&xemb_lo, g_xemb_lo);
    cudaGetSymbolAddress((void**)&h,       g_h);
    cudaGetSymbolAddress((void**)&h_hi,    g_h_hi);
    cudaGetSymbolAddress((void**)&h_lo,    g_h_lo);
    cudaGetSymbolAddress((void**)&hraw,    g_hraw);
    cudaGetSymbolAddress((void**)&c,       g_c);
    cudaGetSymbolAddress((void**)&gates,   g_gates);
    cudaGetSymbolAddress((void**)&wT_hi,   g_wT_hi);
    cudaGetSymbolAddress((void**)&wT_lo,   g_wT_lo);
    cudaGetSymbolAddress((void**)&bcomb,   g_bcomb);
    cudaGetSymbolAddress((void**)&o1,      g_o1);
    cudaGetSymbolAddress((void**)&o2,      g_o2);
    cudaGetSymbolAddress((void**)&o3,      g_o3);

    float* outp = (float*)d_out;

    lane_kernel<<<1, 32>>>(lane, Wlg1, blg1, Wlg2, blg2);
    prep_w<<<(KK * H4 + 255) / 256, 256>>>(Wih, bih, Whh, bhh, wT_hi, wT_lo, bcomb);
    init_hc<<<(SS * HH + 255) / 256, 256>>>(h, c, h_hi, h_lo);

    // Embedding MLP: [S*T, I] -> [S*T, EH] -> split bf16 [T,S,E]
    {
        dim3 g1(1, (SS * TT) / BM);
        gemm_kernel<true, true, false, false><<<g1, NTHREADS>>>(
            inputData, We1, be1, y1, nullptr, nullptr, SS * TT, EHH, II);
        dim3 g2(EE / BN, (SS * TT) / BM);
        gemm_kernel<false, true, true, true><<<g2, NTHREADS>>>(
            y1, We2, be2, nullptr, xemb_hi, xemb_lo, SS * TT, EE, EHH);
    }

    // LSTM over time (tensor-core gates GEMM)
    dim3 gg(H4 / 128, SS / 128);   // (16, 32)
    int pw_blocks = (SS * HH + 255) / 256;
    for (int t = 0; t < TT; t++) {
        size_t xoff = (size_t)t * SS * EE;
        gates_mma<<<gg, 256>>>(xemb_hi + xoff, xemb_lo + xoff, h_hi, h_lo,
                               wT_hi, wT_lo, bcomb, gates);
        lstm_pointwise<<<pw_blocks, 256>>>(gates, c, hraw);
        maxpool_kernel<<<pw_blocks, 256>>>(hraw, h, h_hi, h_lo);
    }

    // Output head (fp32 SIMT)
    gemm_kernel<false, false, false, false><<<dim3(1, SS / BM), NTHREADS>>>(
        h, Wout, bout, o1, nullptr, nullptr, SS, OO, HH);
    gemm_kernel<false, true, false, false><<<dim3(FF1 / BN, SS / BM), NTHREADS>>>(
        o1, Wf1, bf1, o2, nullptr, nullptr, SS, FF1, OO);
    gemm_kernel<false, true, false, false><<<dim3(1, SS / BM), NTHREADS>>>(
        o2, Wf2, bf2, o3, nullptr, nullptr, SS, FF2, FF1);
    final_out<<<(SS * 32 + 127) / 128, 128>>>(Wf3, bf3, o3, outp);
    if (out_size >= SS + 2 * SS * HH) {
        copy_hc<<<pw_blocks, 256>>>(h, c, outp);
    }
}

// round 13
// speedup vs baseline: 2.4249x; 1.0052x over previous
#include <cuda_runtime.h>
#include <cuda_bf16.h>
#include <math.h>
#include <stdint.h>

// Problem dims
#define SS   4096
#define TT   64
#define II   64
#define EHH  128
#define EE   256
#define HH   512
#define H4   2048
#define KK   (EE + HH)   // 768
#define OO   128
#define FF1  256
#define FF2  64
#define LGG  32

// SIMT GEMM tile config
#define BM 128
#define BN 128
#define BK 8
#define TM 8
#define TN 8
#define NTHREADS 256

// ---------------- device scratch (host access ONLY via cudaGetSymbolAddress) ----------------
__device__ float g_laneC;
__device__ float g_y1[(size_t)SS * TT * EHH];
__device__ __nv_bfloat16 g_xemb_hi[(size_t)TT * SS * EE];
__device__ __nv_bfloat16 g_xemb_lo[(size_t)TT * SS * EE];
__device__ float g_h[SS * HH];
__device__ __nv_bfloat16 g_h_hi[SS * HH];
__device__ __nv_bfloat16 g_h_lo[SS * HH];
__device__ float g_hraw[SS * HH];
__device__ float g_c[SS * HH];
__device__ __nv_bfloat16 g_wT_hi[(size_t)KK * H4];   // [768][2048], gate-interleaved cols
__device__ __nv_bfloat16 g_wT_lo[(size_t)KK * H4];
__device__ float g_bcomb[H4];                        // gate-interleaved
__device__ float g_o1[SS * OO];
__device__ float g_o2[SS * FF1];
__device__ float g_o3[SS * FF2];

__device__ __forceinline__ float sigmoidf(float x) {
    return 1.0f / (1.0f + __expf(-x));
}

__device__ __forceinline__ void split2(float v, __nv_bfloat16& hi, __nv_bfloat16& lo) {
    hi = __float2bfloat16(v);
    lo = __float2bfloat16(v - __bfloat162float(hi));
}

// ---------------- tiny kernels ----------------
__global__ void lane_kernel(const float* __restrict__ lane,
                            const float* __restrict__ Wlg1, const float* __restrict__ blg1,
                            const float* __restrict__ Wlg2, const float* __restrict__ blg2) {
    if (threadIdx.x == 0) {
        float l = lane[0];
        float acc = blg2[0];
        for (int j = 0; j < LGG; j++) {
            float v = fmaxf(l * Wlg1[j] + blg1[j], 0.0f);
            acc += v * Wlg2[j];
        }
        g_laneC = 1.0f / (1.0f + expf(-acc));
    }
}

// Transposed combined weight [768][2048], GATE-INTERLEAVED columns:
// col n = 4*j + g  <->  original output row g*512 + j  (g in {i,f,g,o}).
__global__ void prep_w(const float* __restrict__ Wih, const float* __restrict__ bih,
                       const float* __restrict__ Whh, const float* __restrict__ bhh,
                       __nv_bfloat16* __restrict__ wThi, __nv_bfloat16* __restrict__ wTlo,
                       float* __restrict__ bcomb) {
    int idx = blockIdx.x * blockDim.x + threadIdx.x;
    if (idx < KK * H4) {
        int k = idx >> 11;          // / 2048
        int n = idx & (H4 - 1);
        int j = n >> 2, gsel = n & 3;
        int orow = gsel * HH + j;
        float v = (k < EE) ? Wih[(size_t)orow * EE + k] : Whh[(size_t)orow * HH + (k - EE)];
        __nv_bfloat16 hi, lo;
        split2(v, hi, lo);
        wThi[idx] = hi; wTlo[idx] = lo;
    }
    if (idx < H4) {
        int j = idx >> 2, gsel = idx & 3;
        int orow = gsel * HH + j;
        bcomb[idx] = bih[orow] + bhh[orow];
    }
}

__global__ void init_hc(float* __restrict__ h, float* __restrict__ c,
                        __nv_bfloat16* __restrict__ hhi, __nv_bfloat16* __restrict__ hlo) {
    int idx = blockIdx.x * blockDim.x + threadIdx.x;
    if (idx < SS * HH) {
        h[idx] = 0.0f; c[idx] = 0.0f;
        hhi[idx] = __float2bfloat16(0.0f); hlo[idx] = __float2bfloat16(0.0f);
    }
}

// ---------------- SIMT fp32 GEMM (embedding + head) ----------------
template <bool SCALEA, bool RELU, bool REMAP, bool SPLITOUT>
__global__ void __launch_bounds__(NTHREADS)
gemm_kernel(const float* __restrict__ A, const float* __restrict__ B,
            const float* __restrict__ bias, float* __restrict__ Cout,
            __nv_bfloat16* __restrict__ Ohi, __nv_bfloat16* __restrict__ Olo,
            int M, int N, int K) {
    __shared__ float As[BK][BM + 4];
    __shared__ float Bs[BK][BN + 4];

    const int tid = threadIdx.x;
    const int tx = tid & 15;
    const int ty = tid >> 4;
    const int m0 = blockIdx.y * BM;
    const int n0 = blockIdx.x * BN;

    float acc[TM][TN];
#pragma unroll
    for (int i = 0; i < TM; i++)
#pragma unroll
        for (int j = 0; j < TN; j++) acc[i][j] = 0.0f;

    const float scale = SCALEA ? g_laneC : 1.0f;

    for (int k0 = 0; k0 < K; k0 += BK) {
#pragma unroll
        for (int l = 0; l < (BM * BK) / NTHREADS; l++) {
            int idx = tid + l * NTHREADS;
            int r = idx >> 3, c = idx & 7;
            int gm = m0 + r;
            float v = (gm < M) ? A[(size_t)gm * K + (k0 + c)] : 0.0f;
            As[c][r] = v * scale;
        }
#pragma unroll
        for (int l = 0; l < (BN * BK) / NTHREADS; l++) {
            int idx = tid + l * NTHREADS;
            int r = idx >> 3, c = idx & 7;
            int gn = n0 + r;
            float v = (gn < N) ? B[(size_t)gn * K + (k0 + c)] : 0.0f;
            Bs[c][r] = v;
        }
        __syncthreads();

#pragma unroll
        for (int k = 0; k < BK; k++) {
            float a[TM], b[TN];
#pragma unroll
            for (int i = 0; i < TM; i++) a[i] = As[k][ty * TM + i];
#pragma unroll
            for (int j = 0; j < TN; j++) b[j] = Bs[k][tx * TN + j];
#pragma unroll
            for (int i = 0; i < TM; i++)
#pragma unroll
                for (int j = 0; j < TN; j++) acc[i][j] += a[i] * b[j];
        }
        __syncthreads();
    }

#pragma unroll
    for (int i = 0; i < TM; i++) {
        int gm = m0 + ty * TM + i;
        if (gm >= M) continue;
        size_t orow = gm;
        if (REMAP) orow = (size_t)(gm % TT) * SS + (size_t)(gm / TT);
#pragma unroll
        for (int j = 0; j < TN; j++) {
            int gn = n0 + tx * TN + j;
            if (gn < N) {
                float v = acc[i][j] + bias[gn];
                if (RELU) v = fmaxf(v, 0.0f);
                size_t oidx = orow * (size_t)N + gn;
                if (SPLITOUT) {
                    __nv_bfloat16 hi, lo;
                    split2(v, hi, lo);
                    Ohi[oidx] = hi; Olo[oidx] = lo;
                } else {
                    Cout[oidx] = v;
                }
            }
        }
    }
}

// ---------------- fused bf16 tensor-core gates GEMM + LSTM pointwise ----------------
#define MMA16816(d, a, b)                                                     \
    asm volatile(                                                             \
        "mma.sync.aligned.m16n8k16.row.col.f32.bf16.bf16.f32 "                \
        "{%0,%1,%2,%3}, {%4,%5,%6,%7}, {%8,%9}, {%0,%1,%2,%3};"               \
        : "+f"(d[0]), "+f"(d[1]), "+f"(d[2]), "+f"(d[3])                      \
        : "r"(a[0]), "r"(a[1]), "r"(a[2]), "r"(a[3]), "r"(b[0]), "r"(b[1]))

__device__ __forceinline__ void ldsm_x4(uint32_t& r0, uint32_t& r1, uint32_t& r2,
                                        uint32_t& r3, uint32_t addr) {
    asm volatile("ldmatrix.sync.aligned.m8n8.x4.shared.b16 {%0,%1,%2,%3}, [%4];"
                 : "=r"(r0), "=r"(r1), "=r"(r2), "=r"(r3) : "r"(addr));
}
__device__ __forceinline__ void ldsm_x2t(uint32_t& r0, uint32_t& r1, uint32_t addr) {
    asm volatile("ldmatrix.sync.aligned.m8n8.x2.trans.shared.b16 {%0,%1}, [%2];"
                 : "=r"(r0), "=r"(r1) : "r"(addr));
}

#define AST 40    // A smem row stride (b16 elems)
#define BST 136   // B smem row stride

__global__ void __launch_bounds__(256)
gates_mma_fused(const __nv_bfloat16* __restrict__ xhi, const __nv_bfloat16* __restrict__ xlo,
                const __nv_bfloat16* __restrict__ hhi, const __nv_bfloat16* __restrict__ hlo,
                const __nv_bfloat16* __restrict__ wThi, const __nv_bfloat16* __restrict__ wTlo,
                const float* __restrict__ bcomb,
                float* __restrict__ cbuf, float* __restrict__ hraw) {
    __shared__ __nv_bfloat16 Ahi[128][AST];
    __shared__ __nv_bfloat16 Alo[128][AST];
    __shared__ __nv_bfloat16 Bhi[32][BST];
    __shared__ __nv_bfloat16 Blo[32][BST];

    const int tid  = threadIdx.x;
    const int lane = tid & 31;
    const int w    = tid >> 5;
    const int wm   = w & 1;
    const int wn   = w >> 1;
    const int n0   = blockIdx.x * 128;
    const int s0   = blockIdx.y * 128;

    const uint32_t ahi_s = (uint32_t)__cvta_generic_to_shared(&Ahi[0][0]);
    const uint32_t alo_s = (uint32_t)__cvta_generic_to_shared(&Alo[0][0]);
    const uint32_t bhi_s = (uint32_t)__cvta_generic_to_shared(&Bhi[0][0]);
    const uint32_t blo_s = (uint32_t)__cvta_generic_to_shared(&Blo[0][0]);

    float acc[4][4][4];
#pragma unroll
    for (int mt = 0; mt < 4; mt++)
#pragma unroll
        for (int nt = 0; nt < 4; nt++)
#pragma unroll
            for (int e = 0; e < 4; e++) acc[mt][nt][e] = 0.0f;

    for (int k0 = 0; k0 < KK; k0 += 32) {
        // load A tile 128x32 (hi & lo)
        {
            int row = tid >> 1, half = tid & 1;
            const __nv_bfloat16 *sh, *sl;
            if (k0 < EE) {
                size_t off = (size_t)(s0 + row) * EE + k0 + half * 16;
                sh = xhi + off; sl = xlo + off;
            } else {
                size_t off = (size_t)(s0 + row) * HH + (k0 - EE) + half * 16;
                sh = hhi + off; sl = hlo + off;
            }
            *(uint4*)&Ahi[row][half * 16]     = *(const uint4*)sh;
            *(uint4*)&Ahi[row][half * 16 + 8] = *(const uint4*)(sh + 8);
            *(uint4*)&Alo[row][half * 16]     = *(const uint4*)sl;
            *(uint4*)&Alo[row][half * 16 + 8] = *(const uint4*)(sl + 8);
        }
        // load B tile 32x128 (hi & lo)
#pragma unroll
        for (int it = 0; it < 2; it++) {
            int chunk = tid + it * 256;
            int row = chunk >> 4, c = chunk & 15;
            size_t off = (size_t)(k0 + row) * H4 + n0 + c * 8;
            *(uint4*)&Bhi[row][c * 8] = *(const uint4*)(wThi + off);
            *(uint4*)&Blo[row][c * 8] = *(const uint4*)(wTlo + off);
        }
        __syncthreads();

#pragma unroll
        for (int kk = 0; kk < 32; kk += 16) {
            // B fragments via ldmatrix.x2.trans
            uint32_t bh[4][2], bl[4][2];
#pragma unroll
            for (int nt = 0; nt < 4; nt++) {
                int row = kk + (lane & 15);
                int col = wn * 32 + nt * 8;
                uint32_t off = (uint32_t)(row * BST + col) * 2;
                ldsm_x2t(bh[nt][0], bh[nt][1], bhi_s + off);
                ldsm_x2t(bl[nt][0], bl[nt][1], blo_s + off);
            }
            // A fragments via ldmatrix.x4, then MMAs
#pragma unroll
            for (int mt = 0; mt < 4; mt++) {
                int row = wm * 64 + mt * 16 + ((lane >> 3) & 1) * 8 + (lane & 7);
                int col = kk + (lane >> 4) * 8;
                uint32_t off = (uint32_t)(row * AST + col) * 2;
                uint32_t ah[4], al[4];
                ldsm_x4(ah[0], ah[1], ah[2], ah[3], ahi_s + off);
                ldsm_x4(al[0], al[1], al[2], al[3], alo_s + off);
#pragma unroll
                for (int nt = 0; nt < 4; nt++) {
                    MMA16816(acc[mt][nt], ah, bh[nt]);
                    MMA16816(acc[mt][nt], ah, bl[nt]);
                    MMA16816(acc[mt][nt], al, bh[nt]);
                }
            }
        }
        __syncthreads();
    }

    // ---- fused LSTM pointwise epilogue ----
    // col n = 4*j + g. Even lane holds (i,f), odd lane (g,o) of same channel.
    const bool even = ((lane & 1) == 0);
#pragma unroll
    for (int mt = 0; mt < 4; mt++) {
        int r = s0 + wm * 64 + mt * 16 + (lane >> 2);
#pragma unroll
        for (int nt = 0; nt < 4; nt++) {
            int cn = n0 + wn * 32 + nt * 8 + (lane & 3) * 2;
            float x0 = acc[mt][nt][0] + bcomb[cn];
            float x1 = acc[mt][nt][1] + bcomb[cn + 1];
            float x2 = acc[mt][nt][2] + bcomb[cn];
            float x3 = acc[mt][nt][3] + bcomb[cn + 1];

            // even: i0=sig(x0), f0=sig(x1), i8=sig(x2), f8=sig(x3)
            // odd : g0=tanh(x0), o0=sig(x1), g8=tanh(x2), o8=sig(x3)
            float s1 = sigmoidf(x1);
            float s3 = sigmoidf(x3);
            float t0 = even ? sigmoidf(x0) : tanhf(x0);
            float t2 = even ? sigmoidf(x2) : tanhf(x2);

            // exchange: even sends (i8,f8) -> odd; odd sends (g0,o0) -> even
            float recvA = __shfl_xor_sync(0xffffffffu, even ? t2 : t0, 1);
            float recvB = __shfl_xor_sync(0xffffffffu, even ? s3 : s1, 1);

            int rr = even ? r : r + 8;             // even handles row r, odd row r+8
            float iv = even ? t0 : recvA;
            float fv = even ? s1 : recvB;
            float gv = even ? recvA : t2;
            float ov = even ? recvB : s3;

            int j = cn >> 2;
            size_t ci = (size_t)rr * HH + j;
            float cnew = fv * cbuf[ci] + iv * gv;
            cbuf[ci] = cnew;
            hraw[ci] = ov * tanhf(cnew);
        }
    }
}

// ---------------- spatial maxpool (+ bf16 split of h) ----------------
__global__ void maxpool_kernel(const float* __restrict__ hraw, float* __restrict__ h,
                               __nv_bfloat16* __restrict__ hhi, __nv_bfloat16* __restrict__ hlo) {
    int idx = blockIdx.x * blockDim.x + threadIdx.x;
    if (idx >= SS * HH) return;
    int s = idx / HH;
    float v = hraw[idx];
    if (s > 0)      v = fmaxf(v, hraw[idx - HH]);
    if (s < SS - 1) v = fmaxf(v, hraw[idx + HH]);
    h[idx] = v;
    __nv_bfloat16 hi, lo;
    split2(v, hi, lo);
    hhi[idx] = hi; hlo[idx] = lo;
}

// ---------------- final dot + output assembly ----------------
__global__ void final_out(const float* __restrict__ Wf3, const float* __restrict__ bf3,
                          const float* __restrict__ o3, float* __restrict__ outp) {
    int warp = (blockIdx.x * blockDim.x + threadIdx.x) >> 5;
    int lane = threadIdx.x & 31;
    if (warp >= SS) return;
    const float* row = o3 + (size_t)warp * FF2;
    float v = row[lane] * Wf3[lane] + row[lane + 32] * Wf3[lane + 32];
#pragma unroll
    for (int o = 16; o; o >>= 1) v += __shfl_down_sync(0xffffffffu, v, o);
    if (lane == 0) outp[warp] = (v + bf3[0]) / g_laneC;
}

__global__ void copy_hc(const float* __restrict__ h, const float* __restrict__ c,
                        float* __restrict__ outp) {
    int idx = blockIdx.x * blockDim.x + threadIdx.x;
    if (idx >= SS * HH) return;
    outp[SS + idx] = h[idx];
    outp[SS + SS * HH + idx] = c[idx];
}

// ---------------- launch ----------------
extern "C" void kernel_launch(void* const* d_in, const int* in_sizes, int n_in,
                              void* d_out, int out_size) {
    static const int DICT_SIZES[22] = {
        16777216, 1, 32, 32, 32, 1, 8192, 128, 32768, 256, 524288,
        2048, 1048576, 2048, 65536, 128, 32768, 256, 16384, 64, 64, 1
    };
    const float* P[22];
    bool used[64];
    for (int i = 0; i < 64; i++) used[i] = false;
    bool ok = (n_in >= 22);
    for (int p = 0; p < 22 && ok; p++) {
        P[p] = nullptr;
        for (int i = 0; i < n_in; i++) {
            if (!used[i] && in_sizes[i] == DICT_SIZES[p]) {
                P[p] = (const float*)d_in[i];
                used[i] = true;
                break;
            }
        }
        if (!P[p]) ok = false;
    }
    if (!ok) {
        for (int p = 0; p < 22; p++) P[p] = (const float*)d_in[p];
    }

    const float* inputData = P[0];
    const float* lane  = P[1];
    const float* Wlg1  = P[2];  const float* blg1 = P[3];
    const float* Wlg2  = P[4];  const float* blg2 = P[5];
    const float* We1   = P[6];  const float* be1  = P[7];
    const float* We2   = P[8];  const float* be2  = P[9];
    const float* Wih   = P[10]; const float* bih  = P[11];
    const float* Whh   = P[12]; const float* bhh  = P[13];
    const float* Wout  = P[14]; const float* bout = P[15];
    const float* Wf1   = P[16]; const float* bf1  = P[17];
    const float* Wf2   = P[18]; const float* bf2  = P[19];
    const float* Wf3   = P[20]; const float* bf3  = P[21];

    float *y1, *h, *hraw, *c, *bcomb, *o1, *o2, *o3;
    __nv_bfloat16 *xemb_hi, *xemb_lo, *h_hi, *h_lo, *wT_hi, *wT_lo;
    cudaGetSymbolAddress((void**)&y1,      g_y1);
    cudaGetSymbolAddress((void**)&xemb_hi, g_xemb_hi);
    cudaGetSymbolAddress((void**)&xemb_lo, g_xemb_lo);
    cudaGetSymbolAddress((void**)&h,       g_h);
    cudaGetSymbolAddress((void**)&h_hi,    g_h_hi);
    cudaGetSymbolAddress((void**)&h_lo,    g_h_lo);
    cudaGetSymbolAddress((void**)&hraw,    g_hraw);
    cudaGetSymbolAddress((void**)&c,       g_c);
    cudaGetSymbolAddress((void**)&wT_hi,   g_wT_hi);
    cudaGetSymbolAddress((void**)&wT_lo,   g_wT_lo);
    cudaGetSymbolAddress((void**)&bcomb,   g_bcomb);
    cudaGetSymbolAddress((void**)&o1,      g_o1);
    cudaGetSymbolAddress((void**)&o2,      g_o2);
    cudaGetSymbolAddress((void**)&o3,      g_o3);

    float* outp = (float*)d_out;

    lane_kernel<<<1, 32>>>(lane, Wlg1, blg1, Wlg2, blg2);
    prep_w<<<(KK * H4 + 255) / 256, 256>>>(Wih, bih, Whh, bhh, wT_hi, wT_lo, bcomb);
    init_hc<<<(SS * HH + 255) / 256, 256>>>(h, c, h_hi, h_lo);

    // Embedding MLP
    {
        dim3 g1(1, (SS * TT) / BM);
        gemm_kernel<true, true, false, false><<<g1, NTHREADS>>>(
            inputData, We1, be1, y1, nullptr, nullptr, SS * TT, EHH, II);
        dim3 g2(EE / BN, (SS * TT) / BM);
        gemm_kernel<false, true, true, true><<<g2, NTHREADS>>>(
            y1, We2, be2, nullptr, xemb_hi, xemb_lo, SS * TT, EE, EHH);
    }

    // LSTM over time: fused gates GEMM + pointwise, then maxpool
    dim3 gg(H4 / 128, SS / 128);
    int pw_blocks = (SS * HH + 255) / 256;
    for (int t = 0; t < TT; t++) {
        size_t xoff = (size_t)t * SS * EE;
        gates_mma_fused<<<gg, 256>>>(xemb_hi + xoff, xemb_lo + xoff, h_hi, h_lo,
                                     wT_hi, wT_lo, bcomb, c, hraw);
        maxpool_kernel<<<pw_blocks, 256>>>(hraw, h, h_hi, h_lo);
    }

    // Output head (fp32 SIMT)
    gemm_kernel<false, false, false, false><<<dim3(1, SS / BM), NTHREADS>>>(
        h, Wout, bout, o1, nullptr, nullptr, SS, OO, HH);
    gemm_kernel<false, true, false, false><<<dim3(FF1 / BN, SS / BM), NTHREADS>>>(
        o1, Wf1, bf1, o2, nullptr, nullptr, SS, FF1, OO);
    gemm_kernel<false, true, false, false><<<dim3(1, SS / BM), NTHREADS>>>(
        o2, Wf2, bf2, o3, nullptr, nullptr, SS, FF2, FF1);
    final_out<<<(SS * 32 + 127) / 128, 128>>>(Wf3, bf3, o3, outp);
    if (out_size >= SS + 2 * SS * HH) {
        copy_hc<<<pw_blocks, 256>>>(h, c, outp);
    }
}

// round 14
// speedup vs baseline: 2.6319x; 1.0854x over previous
#include <cuda_runtime.h>
#include <cuda_bf16.h>
#include <math.h>
#include <stdint.h>

// Problem dims
#define SS   4096
#define TT   64
#define II   64
#define EHH  128
#define EE   256
#define HH   512
#define H4   2048
#define KK   (EE + HH)   // 768
#define OO   128
#define FF1  256
#define FF2  64
#define LGG  32

// SIMT GEMM tile config
#define BM 128
#define BN 128
#define BK 8
#define TM 8
#define TN 8
#define NTHREADS 256

// MMA tile smem strides
#define AST 40    // A smem row stride (b16 elems) -> 80B rows (16B-aligned)
#define BST 136   // B smem row stride -> 272B rows
#define A_BYTES (128 * AST * 2)                  // 10240
#define B_BYTES (32 * BST * 2)                   // 8704
#define STAGE_BYTES (2 * A_BYTES + 2 * B_BYTES)  // 37888
#define NSTAGE 2
#define SMEM_DYN (NSTAGE * STAGE_BYTES)          // 75776

// ---------------- device scratch (host access ONLY via cudaGetSymbolAddress) ----------------
__device__ float g_laneC;
__device__ float g_y1[(size_t)SS * TT * EHH];
__device__ __nv_bfloat16 g_xemb_hi[(size_t)TT * SS * EE];
__device__ __nv_bfloat16 g_xemb_lo[(size_t)TT * SS * EE];
__device__ float g_h[SS * HH];
__device__ __nv_bfloat16 g_h_hi[SS * HH];
__device__ __nv_bfloat16 g_h_lo[SS * HH];
__device__ float g_hraw[SS * HH];
__device__ float g_c[SS * HH];
__device__ __nv_bfloat16 g_wT_hi[(size_t)KK * H4];   // [768][2048], gate-interleaved cols
__device__ __nv_bfloat16 g_wT_lo[(size_t)KK * H4];
__device__ float g_bcomb[H4];                        // gate-interleaved
__device__ float g_o1[SS * OO];
__device__ float g_o2[SS * FF1];
__device__ float g_o3[SS * FF2];

__device__ __forceinline__ float sigmoidf(float x) {
    return 1.0f / (1.0f + __expf(-x));
}
__device__ __forceinline__ float ftanh(float x) {
    // tanh(x) = 2/(1+e^{-2x}) - 1
    return 2.0f / (1.0f + __expf(-2.0f * x)) - 1.0f;
}

__device__ __forceinline__ void split2(float v, __nv_bfloat16& hi, __nv_bfloat16& lo) {
    hi = __float2bfloat16(v);
    lo = __float2bfloat16(v - __bfloat162float(hi));
}

// ---------------- tiny kernels ----------------
__global__ void lane_kernel(const float* __restrict__ lane,
                            const float* __restrict__ Wlg1, const float* __restrict__ blg1,
                            const float* __restrict__ Wlg2, const float* __restrict__ blg2) {
    if (threadIdx.x == 0) {
        float l = lane[0];
        float acc = blg2[0];
        for (int j = 0; j < LGG; j++) {
            float v = fmaxf(l * Wlg1[j] + blg1[j], 0.0f);
            acc += v * Wlg2[j];
        }
        g_laneC = 1.0f / (1.0f + expf(-acc));
    }
}

// Transposed combined weight [768][2048], GATE-INTERLEAVED columns:
// col n = 4*j + g  <->  original output row g*512 + j  (g in {i,f,g,o}).
__global__ void prep_w(const float* __restrict__ Wih, const float* __restrict__ bih,
                       const float* __restrict__ Whh, const float* __restrict__ bhh,
                       __nv_bfloat16* __restrict__ wThi, __nv_bfloat16* __restrict__ wTlo,
                       float* __restrict__ bcomb) {
    int idx = blockIdx.x * blockDim.x + threadIdx.x;
    if (idx < KK * H4) {
        int k = idx >> 11;          // / 2048
        int n = idx & (H4 - 1);
        int j = n >> 2, gsel = n & 3;
        int orow = gsel * HH + j;
        float v = (k < EE) ? Wih[(size_t)orow * EE + k] : Whh[(size_t)orow * HH + (k - EE)];
        __nv_bfloat16 hi, lo;
        split2(v, hi, lo);
        wThi[idx] = hi; wTlo[idx] = lo;
    }
    if (idx < H4) {
        int j = idx >> 2, gsel = idx & 3;
        int orow = gsel * HH + j;
        bcomb[idx] = bih[orow] + bhh[orow];
    }
}

__global__ void init_hc(float* __restrict__ h, float* __restrict__ c,
                        __nv_bfloat16* __restrict__ hhi, __nv_bfloat16* __restrict__ hlo) {
    int idx = blockIdx.x * blockDim.x + threadIdx.x;
    if (idx < SS * HH) {
        h[idx] = 0.0f; c[idx] = 0.0f;
        hhi[idx] = __float2bfloat16(0.0f); hlo[idx] = __float2bfloat16(0.0f);
    }
}

// ---------------- SIMT fp32 GEMM (embedding + head) ----------------
template <bool SCALEA, bool RELU, bool REMAP, bool SPLITOUT>
__global__ void __launch_bounds__(NTHREADS)
gemm_kernel(const float* __restrict__ A, const float* __restrict__ B,
            const float* __restrict__ bias, float* __restrict__ Cout,
            __nv_bfloat16* __restrict__ Ohi, __nv_bfloat16* __restrict__ Olo,
            int M, int N, int K) {
    __shared__ float As[BK][BM + 4];
    __shared__ float Bs[BK][BN + 4];

    const int tid = threadIdx.x;
    const int tx = tid & 15;
    const int ty = tid >> 4;
    const int m0 = blockIdx.y * BM;
    const int n0 = blockIdx.x * BN;

    float acc[TM][TN];
#pragma unroll
    for (int i = 0; i < TM; i++)
#pragma unroll
        for (int j = 0; j < TN; j++) acc[i][j] = 0.0f;

    const float scale = SCALEA ? g_laneC : 1.0f;

    for (int k0 = 0; k0 < K; k0 += BK) {
#pragma unroll
        for (int l = 0; l < (BM * BK) / NTHREADS; l++) {
            int idx = tid + l * NTHREADS;
            int r = idx >> 3, c = idx & 7;
            int gm = m0 + r;
            float v = (gm < M) ? A[(size_t)gm * K + (k0 + c)] : 0.0f;
            As[c][r] = v * scale;
        }
#pragma unroll
        for (int l = 0; l < (BN * BK) / NTHREADS; l++) {
            int idx = tid + l * NTHREADS;
            int r = idx >> 3, c = idx & 7;
            int gn = n0 + r;
            float v = (gn < N) ? B[(size_t)gn * K + (k0 + c)] : 0.0f;
            Bs[c][r] = v;
        }
        __syncthreads();

#pragma unroll
        for (int k = 0; k < BK; k++) {
            float a[TM], b[TN];
#pragma unroll
            for (int i = 0; i < TM; i++) a[i] = As[k][ty * TM + i];
#pragma unroll
            for (int j = 0; j < TN; j++) b[j] = Bs[k][tx * TN + j];
#pragma unroll
            for (int i = 0; i < TM; i++)
#pragma unroll
                for (int j = 0; j < TN; j++) acc[i][j] += a[i] * b[j];
        }
        __syncthreads();
    }

#pragma unroll
    for (int i = 0; i < TM; i++) {
        int gm = m0 + ty * TM + i;
        if (gm >= M) continue;
        size_t orow = gm;
        if (REMAP) orow = (size_t)(gm % TT) * SS + (size_t)(gm / TT);
#pragma unroll
        for (int j = 0; j < TN; j++) {
            int gn = n0 + tx * TN + j;
            if (gn < N) {
                float v = acc[i][j] + bias[gn];
                if (RELU) v = fmaxf(v, 0.0f);
                size_t oidx = orow * (size_t)N + gn;
                if (SPLITOUT) {
                    __nv_bfloat16 hi, lo;
                    split2(v, hi, lo);
                    Ohi[oidx] = hi; Olo[oidx] = lo;
                } else {
                    Cout[oidx] = v;
                }
            }
        }
    }
}

// ---------------- fused bf16 tensor-core gates GEMM + LSTM pointwise ----------------
#define MMA16816(d, a, b)                                                     \
    asm volatile(                                                             \
        "mma.sync.aligned.m16n8k16.row.col.f32.bf16.bf16.f32 "                \
        "{%0,%1,%2,%3}, {%4,%5,%6,%7}, {%8,%9}, {%0,%1,%2,%3};"               \
        : "+f"(d[0]), "+f"(d[1]), "+f"(d[2]), "+f"(d[3])                      \
        : "r"(a[0]), "r"(a[1]), "r"(a[2]), "r"(a[3]), "r"(b[0]), "r"(b[1]))

__device__ __forceinline__ void ldsm_x4(uint32_t& r0, uint32_t& r1, uint32_t& r2,
                                        uint32_t& r3, uint32_t addr) {
    asm volatile("ldmatrix.sync.aligned.m8n8.x4.shared.b16 {%0,%1,%2,%3}, [%4];"
                 : "=r"(r0), "=r"(r1), "=r"(r2), "=r"(r3) : "r"(addr));
}
__device__ __forceinline__ void ldsm_x2t(uint32_t& r0, uint32_t& r1, uint32_t addr) {
    asm volatile("ldmatrix.sync.aligned.m8n8.x2.trans.shared.b16 {%0,%1}, [%2];"
                 : "=r"(r0), "=r"(r1) : "r"(addr));
}
__device__ __forceinline__ void cp16(uint32_t smem_addr, const void* gptr) {
    asm volatile("cp.async.cg.shared.global [%0], [%1], 16;"
                 :: "r"(smem_addr), "l"(gptr));
}
#define CP_COMMIT() asm volatile("cp.async.commit_group;" ::: "memory")
#define CP_WAIT(n)  asm volatile("cp.async.wait_group %0;" :: "n"(n) : "memory")

__global__ void __launch_bounds__(256)
gates_mma_fused(const __nv_bfloat16* __restrict__ xhi, const __nv_bfloat16* __restrict__ xlo,
                const __nv_bfloat16* __restrict__ hhi, const __nv_bfloat16* __restrict__ hlo,
                const __nv_bfloat16* __restrict__ wThi, const __nv_bfloat16* __restrict__ wTlo,
                const float* __restrict__ bcomb,
                float* __restrict__ cbuf, float* __restrict__ hraw) {
    extern __shared__ char dynsmem[];
    const uint32_t smem_u32 = (uint32_t)__cvta_generic_to_shared(dynsmem);

    const int tid  = threadIdx.x;
    const int lane = tid & 31;
    const int w    = tid >> 5;
    const int wm   = w & 1;
    const int wn   = w >> 1;
    const int n0   = blockIdx.x * 128;
    const int s0   = blockIdx.y * 128;

    float acc[4][4][4];
#pragma unroll
    for (int mt = 0; mt < 4; mt++)
#pragma unroll
        for (int nt = 0; nt < 4; nt++)
#pragma unroll
            for (int e = 0; e < 4; e++) acc[mt][nt][e] = 0.0f;

    const int NIT = KK / 32;   // 24

    // async-load one K-stage (A 128x32 hi/lo, B 32x128 hi/lo)
    auto load_stage = [&](int i) {
        const int k0 = i * 32;
        const uint32_t sb = smem_u32 + (uint32_t)(i & 1) * STAGE_BYTES;
        // A tiles: 512 16B-chunks each for hi and lo
#pragma unroll
        for (int it = 0; it < 2; it++) {
            int chunk = tid + it * 256;
            int row = chunk >> 2, cc = chunk & 3;
            const __nv_bfloat16 *sh, *sl;
            if (k0 < EE) {
                size_t off = (size_t)(s0 + row) * EE + k0 + cc * 8;
                sh = xhi + off; sl = xlo + off;
            } else {
                size_t off = (size_t)(s0 + row) * HH + (k0 - EE) + cc * 8;
                sh = hhi + off; sl = hlo + off;
            }
            uint32_t so = (uint32_t)(row * (AST * 2) + cc * 16);
            cp16(sb + so, sh);
            cp16(sb + A_BYTES + so, sl);
        }
        // B tiles: 512 chunks each for hi and lo
#pragma unroll
        for (int it = 0; it < 2; it++) {
            int chunk = tid + it * 256;
            int row = chunk >> 4, cc = chunk & 15;
            size_t off = (size_t)(k0 + row) * H4 + n0 + cc * 8;
            uint32_t so = (uint32_t)(row * (BST * 2) + cc * 16);
            cp16(sb + 2 * A_BYTES + so, wThi + off);
            cp16(sb + 2 * A_BYTES + B_BYTES + so, wTlo + off);
        }
    };

    load_stage(0);
    CP_COMMIT();

    for (int i = 0; i < NIT; i++) {
        if (i + 1 < NIT) {
            load_stage(i + 1);
            CP_COMMIT();
            CP_WAIT(1);
        } else {
            CP_WAIT(0);
        }
        __syncthreads();

        const uint32_t sb    = smem_u32 + (uint32_t)(i & 1) * STAGE_BYTES;
        const uint32_t ahi_s = sb;
        const uint32_t alo_s = sb + A_BYTES;
        const uint32_t bhi_s = sb + 2 * A_BYTES;
        const uint32_t blo_s = sb + 2 * A_BYTES + B_BYTES;

#pragma unroll
        for (int kk = 0; kk < 32; kk += 16) {
            uint32_t bh[4][2], bl[4][2];
#pragma unroll
            for (int nt = 0; nt < 4; nt++) {
                int row = kk + (lane & 15);
                int col = wn * 32 + nt * 8;
                uint32_t off = (uint32_t)(row * BST + col) * 2;
                ldsm_x2t(bh[nt][0], bh[nt][1], bhi_s + off);
                ldsm_x2t(bl[nt][0], bl[nt][1], blo_s + off);
            }
#pragma unroll
            for (int mt = 0; mt < 4; mt++) {
                int row = wm * 64 + mt * 16 + ((lane >> 3) & 1) * 8 + (lane & 7);
                int col = kk + (lane >> 4) * 8;
                uint32_t off = (uint32_t)(row * AST + col) * 2;
                uint32_t ah[4], al[4];
                ldsm_x4(ah[0], ah[1], ah[2], ah[3], ahi_s + off);
                ldsm_x4(al[0], al[1], al[2], al[3], alo_s + off);
#pragma unroll
                for (int nt = 0; nt < 4; nt++) {
                    MMA16816(acc[mt][nt], ah, bh[nt]);
                    MMA16816(acc[mt][nt], ah, bl[nt]);
                    MMA16816(acc[mt][nt], al, bh[nt]);
                }
            }
        }
        __syncthreads();
    }

    // ---- fused LSTM pointwise epilogue ----
    // col n = 4*j + g. Even lane holds (i,f), odd lane (g,o) of same channel.
    const bool even = ((lane & 1) == 0);
#pragma unroll
    for (int mt = 0; mt < 4; mt++) {
        int r = s0 + wm * 64 + mt * 16 + (lane >> 2);
#pragma unroll
        for (int nt = 0; nt < 4; nt++) {
            int cn = n0 + wn * 32 + nt * 8 + (lane & 3) * 2;
            float x0 = acc[mt][nt][0] + bcomb[cn];
            float x1 = acc[mt][nt][1] + bcomb[cn + 1];
            float x2 = acc[mt][nt][2] + bcomb[cn];
            float x3 = acc[mt][nt][3] + bcomb[cn + 1];

            float s1 = sigmoidf(x1);
            float s3 = sigmoidf(x3);
            float t0 = even ? sigmoidf(x0) : ftanh(x0);
            float t2 = even ? sigmoidf(x2) : ftanh(x2);

            float recvA = __shfl_xor_sync(0xffffffffu, even ? t2 : t0, 1);
            float recvB = __shfl_xor_sync(0xffffffffu, even ? s3 : s1, 1);

            int rr = even ? r : r + 8;
            float iv = even ? t0 : recvA;
            float fv = even ? s1 : recvB;
            float gv = even ? recvA : t2;
            float ov = even ? recvB : s3;

            int j = cn >> 2;
            size_t ci = (size_t)rr * HH + j;
            float cnew = fv * cbuf[ci] + iv * gv;
            cbuf[ci] = cnew;
            hraw[ci] = ov * ftanh(cnew);
        }
    }
}

// ---------------- spatial maxpool (+ bf16 split of h) ----------------
__global__ void maxpool_kernel(const float* __restrict__ hraw, float* __restrict__ h,
                               __nv_bfloat16* __restrict__ hhi, __nv_bfloat16* __restrict__ hlo) {
    int idx = blockIdx.x * blockDim.x + threadIdx.x;
    if (idx >= SS * HH) return;
    int s = idx / HH;
    float v = hraw[idx];
    if (s > 0)      v = fmaxf(v, hraw[idx - HH]);
    if (s < SS - 1) v = fmaxf(v, hraw[idx + HH]);
    h[idx] = v;
    __nv_bfloat16 hi, lo;
    split2(v, hi, lo);
    hhi[idx] = hi; hlo[idx] = lo;
}

// ---------------- final dot + output assembly ----------------
__global__ void final_out(const float* __restrict__ Wf3, const float* __restrict__ bf3,
                          const float* __restrict__ o3, float* __restrict__ outp) {
    int warp = (blockIdx.x * blockDim.x + threadIdx.x) >> 5;
    int lane = threadIdx.x & 31;
    if (warp >= SS) return;
    const float* row = o3 + (size_t)warp * FF2;
    float v = row[lane] * Wf3[lane] + row[lane + 32] * Wf3[lane + 32];
#pragma unroll
    for (int o = 16; o; o >>= 1) v += __shfl_down_sync(0xffffffffu, v, o);
    if (lane == 0) outp[warp] = (v + bf3[0]) / g_laneC;
}

__global__ void copy_hc(const float* __restrict__ h, const float* __restrict__ c,
                        float* __restrict__ outp) {
    int idx = blockIdx.x * blockDim.x + threadIdx.x;
    if (idx >= SS * HH) return;
    outp[SS + idx] = h[idx];
    outp[SS + SS * HH + idx] = c[idx];
}

// ---------------- launch ----------------
extern "C" void kernel_launch(void* const* d_in, const int* in_sizes, int n_in,
                              void* d_out, int out_size) {
    static const int DICT_SIZES[22] = {
        16777216, 1, 32, 32, 32, 1, 8192, 128, 32768, 256, 524288,
        2048, 1048576, 2048, 65536, 128, 32768, 256, 16384, 64, 64, 1
    };
    const float* P[22];
    bool used[64];
    for (int i = 0; i < 64; i++) used[i] = false;
    bool ok = (n_in >= 22);
    for (int p = 0; p < 22 && ok; p++) {
        P[p] = nullptr;
        for (int i = 0; i < n_in; i++) {
            if (!used[i] && in_sizes[i] == DICT_SIZES[p]) {
                P[p] = (const float*)d_in[i];
                used[i] = true;
                break;
            }
        }
        if (!P[p]) ok = false;
    }
    if (!ok) {
        for (int p = 0; p < 22; p++) P[p] = (const float*)d_in[p];
    }

    const float* inputData = P[0];
    const float* lane  = P[1];
    const float* Wlg1  = P[2];  const float* blg1 = P[3];
    const float* Wlg2  = P[4];  const float* blg2 = P[5];
    const float* We1   = P[6];  const float* be1  = P[7];
    const float* We2   = P[8];  const float* be2  = P[9];
    const float* Wih   = P[10]; const float* bih  = P[11];
    const float* Whh   = P[12]; const float* bhh  = P[13];
    const float* Wout  = P[14]; const float* bout = P[15];
    const float* Wf1   = P[16]; const float* bf1  = P[17];
    const float* Wf2   = P[18]; const float* bf2  = P[19];
    const float* Wf3   = P[20]; const float* bf3  = P[21];

    float *y1, *h, *hraw, *c, *bcomb, *o1, *o2, *o3;
    __nv_bfloat16 *xemb_hi, *xemb_lo, *h_hi, *h_lo, *wT_hi, *wT_lo;
    cudaGetSymbolAddress((void**)&y1,      g_y1);
    cudaGetSymbolAddress((void**)&xemb_hi, g_xemb_hi);
    cudaGetSymbolAddress((void**)&xemb_lo, g_xemb_lo);
    cudaGetSymbolAddress((void**)&h,       g_h);
    cudaGetSymbolAddress((void**)&h_hi,    g_h_hi);
    cudaGetSymbolAddress((void**)&h_lo,    g_h_lo);
    cudaGetSymbolAddress((void**)&hraw,    g_hraw);
    cudaGetSymbolAddress((void**)&c,       g_c);
    cudaGetSymbolAddress((void**)&wT_hi,   g_wT_hi);
    cudaGetSymbolAddress((void**)&wT_lo,   g_wT_lo);
    cudaGetSymbolAddress((void**)&bcomb,   g_bcomb);
    cudaGetSymbolAddress((void**)&o1,      g_o1);
    cudaGetSymbolAddress((void**)&o2,      g_o2);
    cudaGetSymbolAddress((void**)&o3,      g_o3);

    float* outp = (float*)d_out;

    // allow 75.8KB dynamic smem (idempotent; host-side attribute, graph-safe)
    cudaFuncSetAttribute(gates_mma_fused,
                         cudaFuncAttributeMaxDynamicSharedMemorySize, SMEM_DYN);

    lane_kernel<<<1, 32>>>(lane, Wlg1, blg1, Wlg2, blg2);
    prep_w<<<(KK * H4 + 255) / 256, 256>>>(Wih, bih, Whh, bhh, wT_hi, wT_lo, bcomb);
    init_hc<<<(SS * HH + 255) / 256, 256>>>(h, c, h_hi, h_lo);

    // Embedding MLP
    {
        dim3 g1(1, (SS * TT) / BM);
        gemm_kernel<true, true, false, false><<<g1, NTHREADS>>>(
            inputData, We1, be1, y1, nullptr, nullptr, SS * TT, EHH, II);
        dim3 g2(EE / BN, (SS * TT) / BM);
        gemm_kernel<false, true, true, true><<<g2, NTHREADS>>>(
            y1, We2, be2, nullptr, xemb_hi, xemb_lo, SS * TT, EE, EHH);
    }

    // LSTM over time: pipelined fused gates GEMM + pointwise, then maxpool
    dim3 gg(H4 / 128, SS / 128);
    int pw_blocks = (SS * HH + 255) / 256;
    for (int t = 0; t < TT; t++) {
        size_t xoff = (size_t)t * SS * EE;
        gates_mma_fused<<<gg, 256, SMEM_DYN>>>(xemb_hi + xoff, xemb_lo + xoff,
                                               h_hi, h_lo, wT_hi, wT_lo, bcomb, c, hraw);
        maxpool_kernel<<<pw_blocks, 256>>>(hraw, h, h_hi, h_lo);
    }

    // Output head (fp32 SIMT)
    gemm_kernel<false, false, false, false><<<dim3(1, SS / BM), NTHREADS>>>(
        h, Wout, bout, o1, nullptr, nullptr, SS, OO, HH);
    gemm_kernel<false, true, false, false><<<dim3(FF1 / BN, SS / BM), NTHREADS>>>(
        o1, Wf1, bf1, o2, nullptr, nullptr, SS, FF1, OO);
    gemm_kernel<false, true, false, false><<<dim3(1, SS / BM), NTHREADS>>>(
        o2, Wf2, bf2, o3, nullptr, nullptr, SS, FF2, FF1);
    final_out<<<(SS * 32 + 127) / 128, 128>>>(Wf3, bf3, o3, outp);
    if (out_size >= SS + 2 * SS * HH) {
        copy_hc<<<pw_blocks, 256>>>(h, c, outp);
    }
}